// round 1
// baseline (speedup 1.0000x reference)
#include <cuda_runtime.h>
#include <math.h>

#define NB    8
#define NS    4096
#define ND    1280
#define NCTX  77
#define NCDIM 2048
#define NADIM 768
#define NHEADS 20
#define NHD   64

// scratch (device globals; no allocation allowed)
__device__ float g_q[NB * NS * ND];      // Q projection  [B,S,D]
__device__ float g_attn[NB * NS * ND];   // attention out [B,S,D]
__device__ float g_k[NB * NCTX * ND];    // K (pre-scaled by 0.125)
__device__ float g_v[NB * NCTX * ND];    // V
__device__ float g_tip[NB * ND];         // adapter @ Wv_adapter
__device__ float g_bias[NB * ND];        // per-batch output bias (tip @ Wo + bo)

// ----------------------------------------------------------------------------
// Tiled SGEMM: C[M,N] = alpha * A[M,K] @ B[K,N]  (+ per-batch bias row)
// 128x128 tile, BK=16, 256 threads, 8x8 microtile.
// Requires: K % 16 == 0, N % 128 == 0, 16B-aligned rows (K,N mult of 4). M guarded.
// ----------------------------------------------------------------------------
template <bool HAS_BIAS>
__global__ __launch_bounds__(256)
void sgemm_kernel(const float* __restrict__ A, const float* __restrict__ B,
                  float* __restrict__ C, int M, int N, int K, float alpha,
                  const float* __restrict__ bias, int rows_per_batch)
{
    __shared__ float As[16][132];   // transposed A tile (padded)
    __shared__ float Bs[16][128];

    const int tid = threadIdx.x;
    const int bm = blockIdx.y * 128;
    const int bn = blockIdx.x * 128;
    const int tx = tid & 15;        // 0..15 -> 8 cols each
    const int ty = tid >> 4;        // 0..15 -> 8 rows each

    const int arow  = tid >> 2;         // 0..63
    const int acol  = (tid & 3) * 4;    // 0,4,8,12
    const int brow  = tid >> 5;         // 0..7
    const int bcol  = (tid & 31) * 4;   // 0..124

    float acc[8][8];
#pragma unroll
    for (int i = 0; i < 8; i++)
#pragma unroll
        for (int j = 0; j < 8; j++) acc[i][j] = 0.f;

    for (int k0 = 0; k0 < K; k0 += 16) {
        // load A tile (transposed into smem), guard M
#pragma unroll
        for (int h = 0; h < 2; h++) {
            int r = bm + arow + h * 64;
            float4 va = make_float4(0.f, 0.f, 0.f, 0.f);
            if (r < M)
                va = *(const float4*)&A[(size_t)r * K + k0 + acol];
            As[acol + 0][arow + h * 64] = va.x;
            As[acol + 1][arow + h * 64] = va.y;
            As[acol + 2][arow + h * 64] = va.z;
            As[acol + 3][arow + h * 64] = va.w;
        }
        // load B tile
#pragma unroll
        for (int h = 0; h < 2; h++) {
            int r = k0 + brow + h * 8;
            *(float4*)&Bs[brow + h * 8][bcol] =
                *(const float4*)&B[(size_t)r * N + bn + bcol];
        }
        __syncthreads();

#pragma unroll
        for (int kk = 0; kk < 16; kk++) {
            float ra[8], rb[8];
#pragma unroll
            for (int i = 0; i < 8; i++) ra[i] = As[kk][ty * 8 + i];
#pragma unroll
            for (int j = 0; j < 8; j++) rb[j] = Bs[kk][tx * 8 + j];
#pragma unroll
            for (int i = 0; i < 8; i++)
#pragma unroll
                for (int j = 0; j < 8; j++)
                    acc[i][j] += ra[i] * rb[j];
        }
        __syncthreads();
    }

    // store (float4 x2 per row), guard M
#pragma unroll
    for (int i = 0; i < 8; i++) {
        int r = bm + ty * 8 + i;
        if (r >= M) continue;
        float bv[8];
        if (HAS_BIAS) {
            int bidx = r / rows_per_batch;
#pragma unroll
            for (int j = 0; j < 8; j++)
                bv[j] = bias[(size_t)bidx * N + bn + tx * 8 + j];
        }
        float out0[4], out1[4];
#pragma unroll
        for (int j = 0; j < 4; j++) {
            float v0 = acc[i][j] * alpha;
            float v1 = acc[i][j + 4] * alpha;
            if (HAS_BIAS) { v0 += bv[j]; v1 += bv[j + 4]; }
            out0[j] = v0; out1[j] = v1;
        }
        float* cp = &C[(size_t)r * N + bn + tx * 8];
        *(float4*)&cp[0] = make_float4(out0[0], out0[1], out0[2], out0[3]);
        *(float4*)&cp[4] = make_float4(out1[0], out1[1], out1[2], out1[3]);
    }
}

// ----------------------------------------------------------------------------
// Attention: per-thread flash over 77 keys. K pre-scaled by 1/sqrt(64).
// grid: (S/128, H, B), block 128 threads (one query row per thread).
// ----------------------------------------------------------------------------
__global__ __launch_bounds__(128)
void attn_kernel(const float* __restrict__ q, const float* __restrict__ k,
                 const float* __restrict__ v, float* __restrict__ out)
{
    __shared__ float ks[NCTX][NHD];
    __shared__ float vs[NCTX][NHD];

    const int b = blockIdx.z;
    const int h = blockIdx.y;
    const int q0 = blockIdx.x * 128;
    const int tid = threadIdx.x;

    for (int idx = tid; idx < NCTX * NHD; idx += 128) {
        int j = idx >> 6, d = idx & 63;
        size_t g = ((size_t)b * NCTX + j) * ND + h * NHD + d;
        ks[j][d] = k[g];
        vs[j][d] = v[g];
    }
    __syncthreads();

    // load this thread's query row (contiguous 256B via float4)
    const size_t qoff = ((size_t)(b * NS + q0 + tid)) * ND + h * NHD;
    float qr[NHD];
#pragma unroll
    for (int d = 0; d < NHD; d += 4) {
        float4 t = *(const float4*)&q[qoff + d];
        qr[d] = t.x; qr[d + 1] = t.y; qr[d + 2] = t.z; qr[d + 3] = t.w;
    }

    float m = -1e30f, l = 0.f;
    float acc[NHD];
#pragma unroll
    for (int d = 0; d < NHD; d++) acc[d] = 0.f;

    for (int j = 0; j < NCTX; j++) {
        float s = 0.f;
#pragma unroll
        for (int d = 0; d < NHD; d++) s += qr[d] * ks[j][d];
        float mn = fmaxf(m, s);
        float corr = __expf(m - mn);
        float p = __expf(s - mn);
        l = l * corr + p;
#pragma unroll
        for (int d = 0; d < NHD; d++) acc[d] = acc[d] * corr + p * vs[j][d];
        m = mn;
    }

    const float inv = 1.f / l;
    float* op = &out[((size_t)(b * NS + q0 + tid)) * ND + h * NHD];
#pragma unroll
    for (int d = 0; d < NHD; d += 4) {
        *(float4*)&op[d] = make_float4(acc[d] * inv, acc[d + 1] * inv,
                                       acc[d + 2] * inv, acc[d + 3] * inv);
    }
}

// ----------------------------------------------------------------------------
// Adapter branch (softmax over 1 key == 1, so out_ip == v_ip broadcast).
// bias[b,:] = (adapter[b] @ Wv_adapter) @ Wo + bo
// ----------------------------------------------------------------------------
__global__ void adapter1_kernel(const float* __restrict__ ad,
                                const float* __restrict__ Wva,
                                float* __restrict__ tip)
{
    int j = blockIdx.x * 256 + threadIdx.x;
    int b = blockIdx.y;
    if (j >= ND) return;
    float s = 0.f;
    for (int a = 0; a < NADIM; a++)
        s += ad[b * NADIM + a] * Wva[(size_t)a * ND + j];
    tip[b * ND + j] = s;
}

__global__ void adapter2_kernel(const float* __restrict__ tip,
                                const float* __restrict__ Wo,
                                const float* __restrict__ bo,
                                float* __restrict__ bias)
{
    int j = blockIdx.x * 256 + threadIdx.x;
    int b = blockIdx.y;
    if (j >= ND) return;
    float s = bo[j];
    for (int kk = 0; kk < ND; kk++)
        s += tip[b * ND + kk] * Wo[(size_t)kk * ND + j];
    bias[b * ND + j] = s;
}

// ----------------------------------------------------------------------------
extern "C" void kernel_launch(void* const* d_in, const int* in_sizes, int n_in,
                              void* d_out, int out_size)
{
    const float* hs   = (const float*)d_in[0];  // [8,4096,1280]
    const float* enc  = (const float*)d_in[1];  // [8,77,2048]
    const float* ad   = (const float*)d_in[2];  // [8,1,768]
    const float* Wq   = (const float*)d_in[3];  // [1280,1280]
    const float* Wk   = (const float*)d_in[4];  // [2048,1280]
    const float* Wv   = (const float*)d_in[5];  // [2048,1280]
    // d_in[6] = Wk_adapter: mathematically unused (softmax over 1 key == 1)
    const float* Wva  = (const float*)d_in[7];  // [768,1280]
    const float* Wo   = (const float*)d_in[8];  // [1280,1280]
    const float* bo   = (const float*)d_in[9];  // [1280]
    float* out = (float*)d_out;

    float *q, *attn_o, *kbuf, *vbuf, *tip, *bias;
    cudaGetSymbolAddress((void**)&q,      g_q);
    cudaGetSymbolAddress((void**)&attn_o, g_attn);
    cudaGetSymbolAddress((void**)&kbuf,   g_k);
    cudaGetSymbolAddress((void**)&vbuf,   g_v);
    cudaGetSymbolAddress((void**)&tip,    g_tip);
    cudaGetSymbolAddress((void**)&bias,   g_bias);

    const int Mq = NB * NS;        // 32768
    const int Mkv = NB * NCTX;     // 616

    // K/V projections (fold 1/sqrt(64) into K)
    sgemm_kernel<false><<<dim3(ND / 128, (Mkv + 127) / 128), 256>>>(
        enc, Wk, kbuf, Mkv, ND, NCDIM, 0.125f, nullptr, 1);
    sgemm_kernel<false><<<dim3(ND / 128, (Mkv + 127) / 128), 256>>>(
        enc, Wv, vbuf, Mkv, ND, NCDIM, 1.0f, nullptr, 1);

    // adapter bias (tiny)
    adapter1_kernel<<<dim3((ND + 255) / 256, NB), 256>>>(ad, Wva, tip);
    adapter2_kernel<<<dim3((ND + 255) / 256, NB), 256>>>(tip, Wo, bo, bias);

    // Q projection
    sgemm_kernel<false><<<dim3(ND / 128, Mq / 128), 256>>>(
        hs, Wq, q, Mq, ND, ND, 1.0f, nullptr, 1);

    // attention
    attn_kernel<<<dim3(NS / 128, NHEADS, NB), 128>>>(q, kbuf, vbuf, attn_o);

    // output projection + per-batch adapter bias (+bo already folded in)
    sgemm_kernel<true><<<dim3(ND / 128, Mq / 128), 256>>>(
        attn_o, Wo, out, Mq, ND, ND, 1.0f, bias, NS);
}

// round 3
// speedup vs baseline: 3.1656x; 3.1656x over previous
#include <cuda_runtime.h>
#include <cstdint>
#include <math.h>

#define NB     8
#define NS     4096
#define ND     1280
#define NCTX   77
#define NCDIM  2048
#define NADIM  768
#define NHEADS 20
#define NHD    64
#define MQ     (NB*NS)     // 32768
#define MKV    616
#define MKV_PAD 640

// ---------------- scratch (device globals; no allocation allowed) -----------
__device__ float g_hs_rn[MQ * ND];          // RN(hidden_states)
__device__ float g_q[MQ * ND];              // Q projection (fp32)
__device__ float g_attn[MQ * ND];           // attention out (tf32-rounded fp32)
__device__ float g_enc_rn[MKV_PAD * NCDIM]; // RN(encoder), padded to 640 rows
__device__ float g_k[MKV * ND];             // K (pre-scaled by 0.125)
__device__ float g_v[MKV * ND];
__device__ float g_wqt[ND * ND];            // W^T, tf32-rounded  [N,K]
__device__ float g_wot[ND * ND];
__device__ float g_wkt[ND * NCDIM];
__device__ float g_wvt[ND * NCDIM];
__device__ float g_tip[NB * ND];
__device__ float g_bias[NB * ND];

__device__ __forceinline__ float rn_tf32(float x) {
    float y;
    asm volatile("cvt.rna.tf32.f32 %0, %1;" : "=f"(y) : "f"(x));
    return y;
}

// ---------------- tf32 mma.sync GEMM ----------------------------------------
// C[M,N] = alpha * A[M,K] @ Bt[N,K]^T (+ per-batch bias row)
// Tile 128x128x32, 256 threads = 8 warps (2x4), warp tile 64x32.
// SW128-style XOR swizzle on 128B smem rows -> conflict-free fragment loads.
#define BM 128
#define BN 128
#define BK 32
#define NSTG 3
#define ATILE 16384                     // 128 rows x 128B
#define STAGE_BYTES (2 * ATILE)
#define GEMM_SMEM (NSTG * STAGE_BYTES)  // 96 KB

__device__ __forceinline__ void mma_tf32(float* d, const uint32_t* a, const uint32_t* b) {
    asm volatile("mma.sync.aligned.m16n8k8.row.col.f32.tf32.tf32.f32 "
                 "{%0,%1,%2,%3}, {%4,%5,%6,%7}, {%8,%9}, {%0,%1,%2,%3};"
                 : "+f"(d[0]), "+f"(d[1]), "+f"(d[2]), "+f"(d[3])
                 : "r"(a[0]), "r"(a[1]), "r"(a[2]), "r"(a[3]),
                   "r"(b[0]), "r"(b[1]));
}

__global__ __launch_bounds__(256, 2)
void tf32_gemm(const float* __restrict__ A, const float* __restrict__ Bt,
               float* __restrict__ C, int M, int K, int Ntot,
               float alpha, const float* __restrict__ bias, int rows_per_batch)
{
    extern __shared__ char smem[];
    const int tid = threadIdx.x;
    const int wid = tid >> 5, lane = tid & 31;
    const int warp_m = wid & 1;          // 0..1  (x64 rows)
    const int warp_n = wid >> 1;         // 0..3  (x32 cols)
    const int bm = blockIdx.y * BM;
    const int bn = blockIdx.x * BN;
    const int S = K / BK;

    const uint32_t sbase = (uint32_t)__cvta_generic_to_shared(smem);

    // -------- loader setup: 4 A-chunks + 4 B-chunks of 16B per thread -------
    const float* gA[4]; const float* gB[4];
    uint32_t sAoff[4], sBoff[4];
#pragma unroll
    for (int i = 0; i < 4; i++) {
        int chunk = tid + i * 256;       // 0..1023
        int row = chunk >> 3;            // 0..127
        int c16 = chunk & 7;             // 16B chunk within the 128B row
        gA[i] = A  + (size_t)(bm + row) * K + c16 * 4;
        gB[i] = Bt + (size_t)(bn + row) * K + c16 * 4;
        uint32_t so = (uint32_t)row * 128 + (uint32_t)((c16 ^ (row & 7)) << 4);
        sAoff[i] = so;
        sBoff[i] = so + ATILE;
    }

#define LOAD_STAGE(t) do {                                                    \
        uint32_t st_ = sbase + (uint32_t)((t) % NSTG) * STAGE_BYTES;          \
        int k0_ = (t) * BK;                                                   \
        _Pragma("unroll")                                                     \
        for (int i_ = 0; i_ < 4; i_++) {                                      \
            asm volatile("cp.async.cg.shared.global [%0], [%1], 16;"          \
                         :: "r"(st_ + sAoff[i_]), "l"(gA[i_] + k0_));         \
            asm volatile("cp.async.cg.shared.global [%0], [%1], 16;"          \
                         :: "r"(st_ + sBoff[i_]), "l"(gB[i_] + k0_));         \
        }                                                                     \
        asm volatile("cp.async.commit_group;" ::: "memory");                  \
    } while (0)

    float acc[4][4][4];
#pragma unroll
    for (int mf = 0; mf < 4; mf++)
#pragma unroll
        for (int nf = 0; nf < 4; nf++)
#pragma unroll
            for (int j = 0; j < 4; j++) acc[mf][nf][j] = 0.f;

    const int rb = lane >> 2;            // 0..7
    const int cb = lane & 3;             // 0..3

    // prologue
    LOAD_STAGE(0);
    LOAD_STAGE(1);

    for (int s = 0; s < S; s++) {
        asm volatile("cp.async.wait_group %0;" :: "n"(1) : "memory");
        __syncthreads();
        if (s + 2 < S) LOAD_STAGE(s + 2);
        else asm volatile("cp.async.commit_group;" ::: "memory");

        const char* stg = smem + (size_t)(s % NSTG) * STAGE_BYTES;
#pragma unroll
        for (int kk = 0; kk < 4; kk++) {
            uint32_t afrag[4][4];
#pragma unroll
            for (int mf = 0; mf < 4; mf++) {
                int r0 = warp_m * 64 + mf * 16 + rb;
                uint32_t a0 = (uint32_t)r0 * 128
                            + (uint32_t)(((2 * kk) ^ rb) << 4) + cb * 4;
                afrag[mf][0] = *(const uint32_t*)(stg + a0);
                afrag[mf][1] = *(const uint32_t*)(stg + a0 + 1024);      // row+8
                afrag[mf][2] = *(const uint32_t*)(stg + (a0 ^ 16));      // col+4
                afrag[mf][3] = *(const uint32_t*)(stg + ((a0 + 1024) ^ 16));
            }
            uint32_t bfrag[4][2];
#pragma unroll
            for (int nf = 0; nf < 4; nf++) {
                int n0 = warp_n * 32 + nf * 8 + rb;
                uint32_t b0 = ATILE + (uint32_t)n0 * 128
                            + (uint32_t)(((2 * kk) ^ rb) << 4) + cb * 4;
                bfrag[nf][0] = *(const uint32_t*)(stg + b0);
                bfrag[nf][1] = *(const uint32_t*)(stg + (b0 ^ 16));      // k+4
            }
#pragma unroll
            for (int mf = 0; mf < 4; mf++)
#pragma unroll
                for (int nf = 0; nf < 4; nf++)
                    mma_tf32(acc[mf][nf], afrag[mf], bfrag[nf]);
        }
        __syncthreads();
    }

    // -------- epilogue --------
#pragma unroll
    for (int mf = 0; mf < 4; mf++) {
        int r0 = bm + warp_m * 64 + mf * 16 + rb;
#pragma unroll
        for (int half = 0; half < 2; half++) {
            int r = r0 + half * 8;
            if (r >= M) continue;
            float* crow = C + (size_t)r * Ntot + bn + warp_n * 32;
            const float* brow = bias
                ? bias + (size_t)(r / rows_per_batch) * Ntot + bn + warp_n * 32
                : nullptr;
#pragma unroll
            for (int nf = 0; nf < 4; nf++) {
                int cc = nf * 8 + cb * 2;
                float2 o;
                o.x = acc[mf][nf][half * 2 + 0] * alpha;
                o.y = acc[mf][nf][half * 2 + 1] * alpha;
                if (bias) { o.x += brow[cc]; o.y += brow[cc + 1]; }
                *(float2*)(crow + cc) = o;
            }
        }
    }
#undef LOAD_STAGE
}

// ---------------- attention (fp32, 77 keys), output tf32-rounded -----------
__global__ __launch_bounds__(128)
void attn_kernel(const float* __restrict__ q, const float* __restrict__ k,
                 const float* __restrict__ v, float* __restrict__ out)
{
    __shared__ float ks[NCTX][NHD];
    __shared__ float vs[NCTX][NHD];

    const int b = blockIdx.z;
    const int h = blockIdx.y;
    const int q0 = blockIdx.x * 128;
    const int tid = threadIdx.x;

    for (int idx = tid; idx < NCTX * NHD; idx += 128) {
        int j = idx >> 6, d = idx & 63;
        size_t g = ((size_t)(b * NCTX + j)) * ND + h * NHD + d;
        ks[j][d] = k[g];
        vs[j][d] = v[g];
    }
    __syncthreads();

    const size_t qoff = ((size_t)(b * NS + q0 + tid)) * ND + h * NHD;
    float qr[NHD];
#pragma unroll
    for (int d = 0; d < NHD; d += 4) {
        float4 t = *(const float4*)&q[qoff + d];
        qr[d] = t.x; qr[d + 1] = t.y; qr[d + 2] = t.z; qr[d + 3] = t.w;
    }

    float m = -1e30f, l = 0.f;
    float acc[NHD];
#pragma unroll
    for (int d = 0; d < NHD; d++) acc[d] = 0.f;

    for (int j = 0; j < NCTX; j++) {
        float s = 0.f;
#pragma unroll
        for (int d = 0; d < NHD; d++) s += qr[d] * ks[j][d];
        float mn = fmaxf(m, s);
        float corr = __expf(m - mn);
        float p = __expf(s - mn);
        l = l * corr + p;
#pragma unroll
        for (int d = 0; d < NHD; d++) acc[d] = acc[d] * corr + p * vs[j][d];
        m = mn;
    }

    const float inv = 1.f / l;
    float* op = &out[((size_t)(b * NS + q0 + tid)) * ND + h * NHD];
#pragma unroll
    for (int d = 0; d < NHD; d += 4) {
        *(float4*)&op[d] = make_float4(rn_tf32(acc[d] * inv), rn_tf32(acc[d + 1] * inv),
                                       rn_tf32(acc[d + 2] * inv), rn_tf32(acc[d + 3] * inv));
    }
}

// ---------------- preprocessing --------------------------------------------
__global__ void rn_copy4(const float4* __restrict__ in, float4* __restrict__ out, long n4)
{
    long i = (long)blockIdx.x * blockDim.x + threadIdx.x;
    if (i < n4) {
        float4 v = in[i];
        v.x = rn_tf32(v.x); v.y = rn_tf32(v.y); v.z = rn_tf32(v.z); v.w = rn_tf32(v.w);
        out[i] = v;
    }
}

__global__ void rn_pad_enc(const float* __restrict__ enc, float* __restrict__ out)
{
    long i = (long)blockIdx.x * blockDim.x + threadIdx.x;
    if (i < (long)MKV_PAD * NCDIM) {
        long row = i / NCDIM;
        out[i] = (row < MKV) ? rn_tf32(enc[i]) : 0.f;
    }
}

// W[K,N] -> Wt[N,K], tf32-rounded
__global__ void transpose_rn_kernel(const float* __restrict__ W, float* __restrict__ Wt,
                                    int K, int N)
{
    __shared__ float t[32][33];
    int k0 = blockIdx.y * 32, n0 = blockIdx.x * 32;
    int x = threadIdx.x, y = threadIdx.y;  // block (32,8)
#pragma unroll
    for (int i = 0; i < 32; i += 8)
        t[y + i][x] = W[(size_t)(k0 + y + i) * N + n0 + x];
    __syncthreads();
#pragma unroll
    for (int i = 0; i < 32; i += 8)
        Wt[(size_t)(n0 + y + i) * K + k0 + x] = rn_tf32(t[x][y + i]);
}

// ---------------- adapter branch (softmax over 1 key == identity) ----------
__global__ void adapter1_kernel(const float* __restrict__ ad,
                                const float* __restrict__ Wva,
                                float* __restrict__ tip)
{
    __shared__ float red[256];
    int b = blockIdx.y;
    int jj = threadIdx.x & 63, ks = threadIdx.x >> 6;
    int j = blockIdx.x * 64 + jj;
    float s = 0.f;
    for (int a = ks; a < NADIM; a += 4)
        s += ad[b * NADIM + a] * Wva[(size_t)a * ND + j];
    red[threadIdx.x] = s;
    __syncthreads();
    if (ks == 0)
        tip[b * ND + j] = red[jj] + red[jj + 64] + red[jj + 128] + red[jj + 192];
}

__global__ void adapter2_kernel(const float* __restrict__ tip,
                                const float* __restrict__ Wo,
                                const float* __restrict__ bo,
                                float* __restrict__ bias)
{
    __shared__ float red[256];
    int b = blockIdx.y;
    int jj = threadIdx.x & 63, ks = threadIdx.x >> 6;
    int j = blockIdx.x * 64 + jj;
    float s = 0.f;
    for (int kk = ks; kk < ND; kk += 4)
        s += tip[b * ND + kk] * Wo[(size_t)kk * ND + j];
    red[threadIdx.x] = s;
    __syncthreads();
    if (ks == 0)
        bias[b * ND + j] = bo[j] + red[jj] + red[jj + 64] + red[jj + 128] + red[jj + 192];
}

// ---------------------------------------------------------------------------
extern "C" void kernel_launch(void* const* d_in, const int* in_sizes, int n_in,
                              void* d_out, int out_size)
{
    const float* hs  = (const float*)d_in[0];
    const float* enc = (const float*)d_in[1];
    const float* ad  = (const float*)d_in[2];
    const float* Wq  = (const float*)d_in[3];
    const float* Wk  = (const float*)d_in[4];
    const float* Wv  = (const float*)d_in[5];
    // d_in[6] = Wk_adapter: unused (softmax over a single key is identically 1)
    const float* Wva = (const float*)d_in[7];
    const float* Wo  = (const float*)d_in[8];
    const float* bo  = (const float*)d_in[9];
    float* out = (float*)d_out;

    float *hs_rn, *q, *attn_o, *enc_rn, *kbuf, *vbuf;
    float *wqt, *wot, *wkt, *wvt, *tip, *bias;
    cudaGetSymbolAddress((void**)&hs_rn,  g_hs_rn);
    cudaGetSymbolAddress((void**)&q,      g_q);
    cudaGetSymbolAddress((void**)&attn_o, g_attn);
    cudaGetSymbolAddress((void**)&enc_rn, g_enc_rn);
    cudaGetSymbolAddress((void**)&kbuf,   g_k);
    cudaGetSymbolAddress((void**)&vbuf,   g_v);
    cudaGetSymbolAddress((void**)&wqt,    g_wqt);
    cudaGetSymbolAddress((void**)&wot,    g_wot);
    cudaGetSymbolAddress((void**)&wkt,    g_wkt);
    cudaGetSymbolAddress((void**)&wvt,    g_wvt);
    cudaGetSymbolAddress((void**)&tip,    g_tip);
    cudaGetSymbolAddress((void**)&bias,   g_bias);

    cudaFuncSetAttribute(tf32_gemm, cudaFuncAttributeMaxDynamicSharedMemorySize, GEMM_SMEM);

    // preprocessing: RN activations, transpose+RN weights
    long n4 = (long)MQ * ND / 4;
    rn_copy4<<<(unsigned)((n4 + 255) / 256), 256>>>((const float4*)hs, (float4*)hs_rn, n4);
    rn_pad_enc<<<(unsigned)(((long)MKV_PAD * NCDIM + 255) / 256), 256>>>(enc, enc_rn);
    transpose_rn_kernel<<<dim3(ND / 32, ND / 32),    dim3(32, 8)>>>(Wq, wqt, ND, ND);
    transpose_rn_kernel<<<dim3(ND / 32, NCDIM / 32), dim3(32, 8)>>>(Wk, wkt, NCDIM, ND);
    transpose_rn_kernel<<<dim3(ND / 32, NCDIM / 32), dim3(32, 8)>>>(Wv, wvt, NCDIM, ND);
    transpose_rn_kernel<<<dim3(ND / 32, ND / 32),    dim3(32, 8)>>>(Wo, wot, ND, ND);

    // adapter bias (fp32, tiny)
    adapter1_kernel<<<dim3(ND / 64, NB), 256>>>(ad, Wva, tip);
    adapter2_kernel<<<dim3(ND / 64, NB), 256>>>(tip, Wo, bo, bias);

    // K/V projections (fold 1/sqrt(64) into K)
    tf32_gemm<<<dim3(ND / 128, MKV_PAD / 128), 256, GEMM_SMEM>>>(
        enc_rn, wkt, kbuf, MKV, NCDIM, ND, 0.125f, nullptr, 1);
    tf32_gemm<<<dim3(ND / 128, MKV_PAD / 128), 256, GEMM_SMEM>>>(
        enc_rn, wvt, vbuf, MKV, NCDIM, ND, 1.0f, nullptr, 1);

    // Q projection
    tf32_gemm<<<dim3(ND / 128, MQ / 128), 256, GEMM_SMEM>>>(
        hs_rn, wqt, q, MQ, ND, ND, 1.0f, nullptr, 1);

    // attention (fp32; output tf32-rounded for the O-proj operand)
    attn_kernel<<<dim3(NS / 128, NHEADS, NB), 128>>>(q, kbuf, vbuf, attn_o);

    // output projection + per-batch adapter bias (bo folded into bias)
    tf32_gemm<<<dim3(ND / 128, MQ / 128), 256, GEMM_SMEM>>>(
        attn_o, wot, out, MQ, ND, ND, 1.0f, bias, NS);
}

// round 4
// speedup vs baseline: 3.2044x; 1.0123x over previous
#include <cuda_runtime.h>
#include <cstdint>
#include <math.h>

#define NB     8
#define NS     4096
#define ND     1280
#define NCTX   77
#define NCDIM  2048
#define NADIM  768
#define NHEADS 20
#define NHD    64
#define MQ     (NB*NS)     // 32768
#define MKV    616
#define MKV_PAD 640

// ---------------- scratch (device globals; no allocation allowed) -----------
__device__ float g_hs_rn[MQ * ND];          // RN(hidden_states)
__device__ float g_q[MQ * ND];              // Q projection (fp32)
__device__ float g_attn[MQ * ND];           // attention out (tf32-rounded fp32)
__device__ float g_enc_rn[MKV_PAD * NCDIM]; // RN(encoder), padded to 640 rows
__device__ float g_k[MKV * ND];             // K (pre-scaled by 0.125)
__device__ float g_v[MKV * ND];
__device__ float g_wqt[ND * ND];            // W^T, tf32-rounded  [N,K]
__device__ float g_wot[ND * ND];
__device__ float g_wkt[ND * NCDIM];
__device__ float g_wvt[ND * NCDIM];
__device__ float g_tip[NB * ND];
__device__ float g_bias[NB * ND];

__device__ __forceinline__ float rn_tf32(float x) {
    float y;
    asm volatile("cvt.rna.tf32.f32 %0, %1;" : "=f"(y) : "f"(x));
    return y;
}

// ---------------- tf32 mma.sync GEMM ----------------------------------------
// C[M,N] = alpha * A[M,K] @ Bt[N,K]^T (+ per-batch bias row)
// Tile 128x128x32, 128 threads = 4 warps (2x2), warp tile 64x64.
// SW128-style XOR swizzle on 128B smem rows -> conflict-free fragment loads.
#define BM 128
#define BN 128
#define BK 32
#define NSTG 3
#define ATILE 16384                     // 128 rows x 128B
#define STAGE_BYTES (2 * ATILE)
#define GEMM_SMEM (NSTG * STAGE_BYTES)  // 96 KB

__device__ __forceinline__ void mma_tf32(float* d, const uint32_t* a, const uint32_t* b) {
    asm volatile("mma.sync.aligned.m16n8k8.row.col.f32.tf32.tf32.f32 "
                 "{%0,%1,%2,%3}, {%4,%5,%6,%7}, {%8,%9}, {%0,%1,%2,%3};"
                 : "+f"(d[0]), "+f"(d[1]), "+f"(d[2]), "+f"(d[3])
                 : "r"(a[0]), "r"(a[1]), "r"(a[2]), "r"(a[3]),
                   "r"(b[0]), "r"(b[1]));
}

__global__ __launch_bounds__(128, 2)
void tf32_gemm(const float* __restrict__ A, const float* __restrict__ Bt,
               float* __restrict__ C, int M, int K, int Ntot,
               float alpha, const float* __restrict__ bias, int rows_per_batch)
{
    extern __shared__ char smem[];
    const int tid = threadIdx.x;
    const int wid = tid >> 5, lane = tid & 31;
    const int warp_m = wid & 1;          // 0..1  (x64 rows)
    const int warp_n = wid >> 1;         // 0..1  (x64 cols)
    const int bm = blockIdx.y * BM;
    const int bn = blockIdx.x * BN;
    const int S = K / BK;

    const uint32_t sbase = (uint32_t)__cvta_generic_to_shared(smem);

    // -------- loader: 8 A-chunks + 8 B-chunks of 16B per thread -------------
    // chunk i = tid + i*128: row = tid>>3 + i*16 (low 3 bits invariant),
    // c16 = tid&7 invariant -> single base pointer + stride per array.
    const int lrow = tid >> 3;           // 0..15
    const int lc16 = tid & 7;
    const float* gA0 = A  + (size_t)(bm + lrow) * K + lc16 * 4;
    const float* gB0 = Bt + (size_t)(bn + lrow) * K + lc16 * 4;
    const size_t gstep = (size_t)16 * K;            // +16 rows (floats)
    const uint32_t so0 = (uint32_t)lrow * 128 + (uint32_t)((lc16 ^ (lrow & 7)) << 4);

#define LOAD_STAGE(t) do {                                                    \
        uint32_t st_ = sbase + (uint32_t)((t) % NSTG) * STAGE_BYTES;          \
        int k0_ = (t) * BK;                                                   \
        _Pragma("unroll")                                                     \
        for (int i_ = 0; i_ < 8; i_++) {                                      \
            asm volatile("cp.async.cg.shared.global [%0], [%1], 16;"          \
                :: "r"(st_ + so0 + i_ * 2048u), "l"(gA0 + k0_ + i_ * gstep)); \
            asm volatile("cp.async.cg.shared.global [%0], [%1], 16;"          \
                :: "r"(st_ + ATILE + so0 + i_ * 2048u),                       \
                   "l"(gB0 + k0_ + i_ * gstep));                              \
        }                                                                     \
        asm volatile("cp.async.commit_group;" ::: "memory");                  \
    } while (0)

    float acc[4][8][4];
#pragma unroll
    for (int mf = 0; mf < 4; mf++)
#pragma unroll
        for (int nf = 0; nf < 8; nf++)
#pragma unroll
            for (int j = 0; j < 4; j++) acc[mf][nf][j] = 0.f;

    const int rb = lane >> 2;            // 0..7
    const int cb = lane & 3;             // 0..3

    // prologue
    LOAD_STAGE(0);
    LOAD_STAGE(1);

    for (int s = 0; s < S; s++) {
        asm volatile("cp.async.wait_group %0;" :: "n"(1) : "memory");
        __syncthreads();
        if (s + 2 < S) LOAD_STAGE(s + 2);
        else asm volatile("cp.async.commit_group;" ::: "memory");

        const char* stg = smem + (size_t)(s % NSTG) * STAGE_BYTES;
#pragma unroll
        for (int kk = 0; kk < 4; kk++) {
            uint32_t afrag[4][4];
#pragma unroll
            for (int mf = 0; mf < 4; mf++) {
                int r0 = warp_m * 64 + mf * 16 + rb;
                uint32_t a0 = (uint32_t)r0 * 128
                            + (uint32_t)(((2 * kk) ^ rb) << 4) + cb * 4;
                afrag[mf][0] = *(const uint32_t*)(stg + a0);
                afrag[mf][1] = *(const uint32_t*)(stg + a0 + 1024);      // row+8
                afrag[mf][2] = *(const uint32_t*)(stg + (a0 ^ 16));      // k+4
                afrag[mf][3] = *(const uint32_t*)(stg + ((a0 + 1024) ^ 16));
            }
            uint32_t bfrag[8][2];
#pragma unroll
            for (int nf = 0; nf < 8; nf++) {
                int n0 = warp_n * 64 + nf * 8 + rb;
                uint32_t b0 = ATILE + (uint32_t)n0 * 128
                            + (uint32_t)(((2 * kk) ^ rb) << 4) + cb * 4;
                bfrag[nf][0] = *(const uint32_t*)(stg + b0);
                bfrag[nf][1] = *(const uint32_t*)(stg + (b0 ^ 16));      // k+4
            }
#pragma unroll
            for (int mf = 0; mf < 4; mf++)
#pragma unroll
                for (int nf = 0; nf < 8; nf++)
                    mma_tf32(acc[mf][nf], afrag[mf], bfrag[nf]);
        }
        __syncthreads();
    }

    // -------- epilogue --------
#pragma unroll
    for (int mf = 0; mf < 4; mf++) {
        int r0 = bm + warp_m * 64 + mf * 16 + rb;
#pragma unroll
        for (int half = 0; half < 2; half++) {
            int r = r0 + half * 8;
            if (r >= M) continue;
            float* crow = C + (size_t)r * Ntot + bn + warp_n * 64;
            const float* brow = bias
                ? bias + (size_t)(r / rows_per_batch) * Ntot + bn + warp_n * 64
                : nullptr;
#pragma unroll
            for (int nf = 0; nf < 8; nf++) {
                int cc = nf * 8 + cb * 2;
                float2 o;
                o.x = acc[mf][nf][half * 2 + 0] * alpha;
                o.y = acc[mf][nf][half * 2 + 1] * alpha;
                if (bias) { o.x += brow[cc]; o.y += brow[cc + 1]; }
                *(float2*)(crow + cc) = o;
            }
        }
    }
#undef LOAD_STAGE
}

// ---------------- attention: two-pass softmax, scores in smem ---------------
// Block 128 threads (one query row each). smem: K 77x64, V 77x64, S 77x128.
#define ATTN_SMEM ((2 * NCTX * NHD + NCTX * 128) * 4)   // 78848 B

__global__ __launch_bounds__(128)
void attn_kernel(const float* __restrict__ q, const float* __restrict__ k,
                 const float* __restrict__ v, float* __restrict__ out)
{
    extern __shared__ float sm[];
    float* ks = sm;                      // [77][64]
    float* vs = sm + NCTX * NHD;         // [77][64]
    float* sc = sm + 2 * NCTX * NHD;     // [77][128]

    const int b = blockIdx.z;
    const int h = blockIdx.y;
    const int q0 = blockIdx.x * 128;
    const int tid = threadIdx.x;

    for (int idx = tid; idx < NCTX * NHD; idx += 128) {
        int j = idx >> 6, d = idx & 63;
        size_t g = ((size_t)(b * NCTX + j)) * ND + h * NHD + d;
        ks[idx] = k[g];
        vs[idx] = v[g];
    }
    __syncthreads();

    const size_t qoff = ((size_t)(b * NS + q0 + tid)) * ND + h * NHD;
    float qr[NHD];
#pragma unroll
    for (int d = 0; d < NHD; d += 4) {
        float4 t = *(const float4*)&q[qoff + d];
        qr[d] = t.x; qr[d + 1] = t.y; qr[d + 2] = t.z; qr[d + 3] = t.w;
    }

    // pass 1: all scores + max
    float m = -1e30f;
    for (int j = 0; j < NCTX; j++) {
        const float4* kp = (const float4*)(ks + j * NHD);
        float s = 0.f;
#pragma unroll
        for (int d4 = 0; d4 < NHD / 4; d4++) {
            float4 kv = kp[d4];
            s += qr[d4 * 4 + 0] * kv.x + qr[d4 * 4 + 1] * kv.y
               + qr[d4 * 4 + 2] * kv.z + qr[d4 * 4 + 3] * kv.w;
        }
        sc[j * 128 + tid] = s;
        m = fmaxf(m, s);
    }

    // pass 2: unscaled accumulation
    float l = 0.f;
    float acc[NHD];
#pragma unroll
    for (int d = 0; d < NHD; d++) acc[d] = 0.f;

    for (int j = 0; j < NCTX; j++) {
        float p = __expf(sc[j * 128 + tid] - m);
        l += p;
        const float4* vp = (const float4*)(vs + j * NHD);
#pragma unroll
        for (int d4 = 0; d4 < NHD / 4; d4++) {
            float4 vv = vp[d4];
            acc[d4 * 4 + 0] += p * vv.x;
            acc[d4 * 4 + 1] += p * vv.y;
            acc[d4 * 4 + 2] += p * vv.z;
            acc[d4 * 4 + 3] += p * vv.w;
        }
    }

    const float inv = 1.f / l;
    float* op = &out[((size_t)(b * NS + q0 + tid)) * ND + h * NHD];
#pragma unroll
    for (int d = 0; d < NHD; d += 4) {
        *(float4*)&op[d] = make_float4(rn_tf32(acc[d] * inv), rn_tf32(acc[d + 1] * inv),
                                       rn_tf32(acc[d + 2] * inv), rn_tf32(acc[d + 3] * inv));
    }
}

// ---------------- preprocessing --------------------------------------------
__global__ void rn_copy4(const float4* __restrict__ in, float4* __restrict__ out, long n4)
{
    long i = (long)blockIdx.x * blockDim.x + threadIdx.x;
    if (i < n4) {
        float4 v = in[i];
        v.x = rn_tf32(v.x); v.y = rn_tf32(v.y); v.z = rn_tf32(v.z); v.w = rn_tf32(v.w);
        out[i] = v;
    }
}

__global__ void rn_pad_enc(const float* __restrict__ enc, float* __restrict__ out)
{
    long i = (long)blockIdx.x * blockDim.x + threadIdx.x;
    if (i < (long)MKV_PAD * NCDIM) {
        long row = i / NCDIM;
        out[i] = (row < MKV) ? rn_tf32(enc[i]) : 0.f;
    }
}

// W[K,N] -> Wt[N,K], tf32-rounded
__global__ void transpose_rn_kernel(const float* __restrict__ W, float* __restrict__ Wt,
                                    int K, int N)
{
    __shared__ float t[32][33];
    int k0 = blockIdx.y * 32, n0 = blockIdx.x * 32;
    int x = threadIdx.x, y = threadIdx.y;  // block (32,8)
#pragma unroll
    for (int i = 0; i < 32; i += 8)
        t[y + i][x] = W[(size_t)(k0 + y + i) * N + n0 + x];
    __syncthreads();
#pragma unroll
    for (int i = 0; i < 32; i += 8)
        Wt[(size_t)(n0 + y + i) * K + k0 + x] = rn_tf32(t[x][y + i]);
}

// ---------------- adapter branch (softmax over 1 key == identity) ----------
__global__ void adapter1_kernel(const float* __restrict__ ad,
                                const float* __restrict__ Wva,
                                float* __restrict__ tip)
{
    __shared__ float red[256];
    int b = blockIdx.y;
    int jj = threadIdx.x & 63, ks = threadIdx.x >> 6;
    int j = blockIdx.x * 64 + jj;
    float s = 0.f;
    for (int a = ks; a < NADIM; a += 4)
        s += ad[b * NADIM + a] * Wva[(size_t)a * ND + j];
    red[threadIdx.x] = s;
    __syncthreads();
    if (ks == 0)
        tip[b * ND + j] = red[jj] + red[jj + 64] + red[jj + 128] + red[jj + 192];
}

__global__ void adapter2_kernel(const float* __restrict__ tip,
                                const float* __restrict__ Wo,
                                const float* __restrict__ bo,
                                float* __restrict__ bias)
{
    __shared__ float red[256];
    int b = blockIdx.y;
    int jj = threadIdx.x & 63, ks = threadIdx.x >> 6;
    int j = blockIdx.x * 64 + jj;
    float s = 0.f;
    for (int kk = ks; kk < ND; kk += 4)
        s += tip[b * ND + kk] * Wo[(size_t)kk * ND + j];
    red[threadIdx.x] = s;
    __syncthreads();
    if (ks == 0)
        bias[b * ND + j] = bo[j] + red[jj] + red[jj + 64] + red[jj + 128] + red[jj + 192];
}

// ---------------------------------------------------------------------------
extern "C" void kernel_launch(void* const* d_in, const int* in_sizes, int n_in,
                              void* d_out, int out_size)
{
    const float* hs  = (const float*)d_in[0];
    const float* enc = (const float*)d_in[1];
    const float* ad  = (const float*)d_in[2];
    const float* Wq  = (const float*)d_in[3];
    const float* Wk  = (const float*)d_in[4];
    const float* Wv  = (const float*)d_in[5];
    // d_in[6] = Wk_adapter: unused (softmax over a single key is identically 1)
    const float* Wva = (const float*)d_in[7];
    const float* Wo  = (const float*)d_in[8];
    const float* bo  = (const float*)d_in[9];
    float* out = (float*)d_out;

    float *hs_rn, *q, *attn_o, *enc_rn, *kbuf, *vbuf;
    float *wqt, *wot, *wkt, *wvt, *tip, *bias;
    cudaGetSymbolAddress((void**)&hs_rn,  g_hs_rn);
    cudaGetSymbolAddress((void**)&q,      g_q);
    cudaGetSymbolAddress((void**)&attn_o, g_attn);
    cudaGetSymbolAddress((void**)&enc_rn, g_enc_rn);
    cudaGetSymbolAddress((void**)&kbuf,   g_k);
    cudaGetSymbolAddress((void**)&vbuf,   g_v);
    cudaGetSymbolAddress((void**)&wqt,    g_wqt);
    cudaGetSymbolAddress((void**)&wot,    g_wot);
    cudaGetSymbolAddress((void**)&wkt,    g_wkt);
    cudaGetSymbolAddress((void**)&wvt,    g_wvt);
    cudaGetSymbolAddress((void**)&tip,    g_tip);
    cudaGetSymbolAddress((void**)&bias,   g_bias);

    cudaFuncSetAttribute(tf32_gemm, cudaFuncAttributeMaxDynamicSharedMemorySize, GEMM_SMEM);
    cudaFuncSetAttribute(attn_kernel, cudaFuncAttributeMaxDynamicSharedMemorySize, ATTN_SMEM);

    // preprocessing: RN activations, transpose+RN weights
    long n4 = (long)MQ * ND / 4;
    rn_copy4<<<(unsigned)((n4 + 255) / 256), 256>>>((const float4*)hs, (float4*)hs_rn, n4);
    rn_pad_enc<<<(unsigned)(((long)MKV_PAD * NCDIM + 255) / 256), 256>>>(enc, enc_rn);
    transpose_rn_kernel<<<dim3(ND / 32, ND / 32),    dim3(32, 8)>>>(Wq, wqt, ND, ND);
    transpose_rn_kernel<<<dim3(ND / 32, NCDIM / 32), dim3(32, 8)>>>(Wk, wkt, NCDIM, ND);
    transpose_rn_kernel<<<dim3(ND / 32, NCDIM / 32), dim3(32, 8)>>>(Wv, wvt, NCDIM, ND);
    transpose_rn_kernel<<<dim3(ND / 32, ND / 32),    dim3(32, 8)>>>(Wo, wot, ND, ND);

    // adapter bias (fp32, tiny)
    adapter1_kernel<<<dim3(ND / 64, NB), 256>>>(ad, Wva, tip);
    adapter2_kernel<<<dim3(ND / 64, NB), 256>>>(tip, Wo, bo, bias);

    // K/V projections (fold 1/sqrt(64) into K)
    tf32_gemm<<<dim3(ND / 128, MKV_PAD / 128), 128, GEMM_SMEM>>>(
        enc_rn, wkt, kbuf, MKV, NCDIM, ND, 0.125f, nullptr, 1);
    tf32_gemm<<<dim3(ND / 128, MKV_PAD / 128), 128, GEMM_SMEM>>>(
        enc_rn, wvt, vbuf, MKV, NCDIM, ND, 1.0f, nullptr, 1);

    // Q projection
    tf32_gemm<<<dim3(ND / 128, MQ / 128), 128, GEMM_SMEM>>>(
        hs_rn, wqt, q, MQ, ND, ND, 1.0f, nullptr, 1);

    // attention (fp32; output tf32-rounded for the O-proj operand)
    attn_kernel<<<dim3(NS / 128, NHEADS, NB), 128, ATTN_SMEM>>>(q, kbuf, vbuf, attn_o);

    // output projection + per-batch adapter bias (bo folded into bias)
    tf32_gemm<<<dim3(ND / 128, MQ / 128), 128, GEMM_SMEM>>>(
        attn_o, wot, out, MQ, ND, ND, 1.0f, bias, NS);
}